// round 14
// baseline (speedup 1.0000x reference)
#include <cuda_runtime.h>
#include <cuda_bf16.h>
#include <cstdint>
#include <cstddef>

#define BB 64
#define TT 512
#define DD 512
#define NG 4          /* batch groups */
#define CPG 32        /* CTAs per group (j split) */
#define BPG 16        /* batch columns per group */
#define JPC 16        /* j rows per CTA */

/* scan smem */
#define RSTRB 1040
#define OFF_T1 0
#define OFF_T2 66560
#define OFF_P  133120
#define OFF_HO 142080
#define OFF_CO 143168
#define OFF_HP 144256
#define SMEM_SCAN 145280

/* phase-1 tensor GEMM: tile 128m x 64n, 3-stage pipeline, 2 CTAs/SM */
#define GSTR 80
#define GSTAGE 30720
#define SMEM_GEMM 92160

#define PSTR 70

// ---------------- scratch ---------------------------------------------------
__device__ float g_pre[3][(size_t)TT * DD * BB];          // [z][t][j][b]
__device__ unsigned short g_hs[NG][2][2][BPG][DD];        // h split bf16
__device__ unsigned int g_flag[128];                      // per-CTA publish flags
__device__ __nv_bfloat16 g_Xs[2][(size_t)BB * TT * DD];
__device__ __nv_bfloat16 g_Ws[3][2][DD * DD];

// ---------------- helpers ----------------------------------------------------
__device__ __forceinline__ void cp16(uint32_t dst, const void* src) {
    asm volatile("cp.async.cg.shared.global [%0], [%1], 16;" :: "r"(dst), "l"(src));
}
__device__ __forceinline__ void cp_commit() {
    asm volatile("cp.async.commit_group;" ::: "memory");
}
template <int N> __device__ __forceinline__ void cp_wait() {
    asm volatile("cp.async.wait_group %0;" :: "n"(N) : "memory");
}
__device__ __forceinline__ void red_release(unsigned int* p) {
    asm volatile("red.release.gpu.add.u32 [%0], 1;" :: "l"(p) : "memory");
}
__device__ __forceinline__ unsigned ld_acq(const unsigned int* p) {
    unsigned v;
    asm volatile("ld.acquire.gpu.u32 %0, [%1];" : "=r"(v) : "l"(p) : "memory");
    return v;
}
__device__ __forceinline__ void ldsm_x4(uint32_t* r, uint32_t addr) {
    asm volatile("ldmatrix.sync.aligned.m8n8.x4.shared.b16 {%0,%1,%2,%3}, [%4];"
                 : "=r"(r[0]), "=r"(r[1]), "=r"(r[2]), "=r"(r[3]) : "r"(addr));
}
__device__ __forceinline__ void ldsm_x2(uint32_t* r, uint32_t addr) {
    asm volatile("ldmatrix.sync.aligned.m8n8.x2.shared.b16 {%0,%1}, [%2];"
                 : "=r"(r[0]), "=r"(r[1]) : "r"(addr));
}
__device__ __forceinline__ void mma_bf16(float* d, const uint32_t* a, const uint32_t* b) {
    asm volatile(
        "mma.sync.aligned.m16n8k16.row.col.f32.bf16.bf16.f32 "
        "{%0,%1,%2,%3},{%4,%5,%6,%7},{%8,%9},{%0,%1,%2,%3};"
        : "+f"(d[0]), "+f"(d[1]), "+f"(d[2]), "+f"(d[3])
        : "r"(a[0]), "r"(a[1]), "r"(a[2]), "r"(a[3]), "r"(b[0]), "r"(b[1]));
}
__device__ __forceinline__ uint2 split4(float4 v, uint2& lo) {
    __nv_bfloat16 h0 = __float2bfloat16(v.x), h1 = __float2bfloat16(v.y);
    __nv_bfloat16 h2 = __float2bfloat16(v.z), h3 = __float2bfloat16(v.w);
    __nv_bfloat16 l0 = __float2bfloat16(v.x - __bfloat162float(h0));
    __nv_bfloat16 l1 = __float2bfloat16(v.y - __bfloat162float(h1));
    __nv_bfloat16 l2 = __float2bfloat16(v.z - __bfloat162float(h2));
    __nv_bfloat16 l3 = __float2bfloat16(v.w - __bfloat162float(h3));
    __nv_bfloat162 hp0{h0, h1}, hp1{h2, h3}, lp0{l0, l1}, lp1{l2, l3};
    uint2 hi;
    hi.x = *(unsigned*)&hp0; hi.y = *(unsigned*)&hp1;
    lo.x = *(unsigned*)&lp0; lo.y = *(unsigned*)&lp1;
    return hi;
}
__device__ __forceinline__ float sigf(float x) {
    return __fdividef(1.f, 1.f + __expf(-x));
}
__device__ __forceinline__ float tanhfast(float x) {
    const float a = fabsf(x);
    const float e = __expf(2.f * a);
    const float r = 1.f - __fdividef(2.f, e + 1.f);
    return copysignf(r, x);
}

// ---------------- Phase 0: split X/W into bf16 hi/lo, init scan state --------
__global__ void __launch_bounds__(256)
split_kernel(const float* __restrict__ X, const float* __restrict__ Wi,
             const float* __restrict__ Wc, const float* __restrict__ Wo)
{
    const int i = blockIdx.x * 256 + threadIdx.x;
    if (i < BB * TT * (DD / 4)) {
        const int m = i >> 7, k4 = i & 127;
        const int b = m & 63, t = m >> 6;
        const float4 v = __ldg((const float4*)X + ((size_t)b * TT + t) * 128 + k4);
        uint2 lo;
        const uint2 hi = split4(v, lo);
        *(uint2*)&g_Xs[0][(size_t)m * DD + k4 * 4] = hi;
        *(uint2*)&g_Xs[1][(size_t)m * DD + k4 * 4] = lo;
    }
    if (i < 3 * DD * (DD / 4)) {
        const int z = i / (DD * 128);
        const int r = i - z * (DD * 128);
        const int n = r >> 7, k4 = r & 127;
        const float* W = (z == 0) ? Wi : (z == 1) ? Wc : Wo;
        const float4 v = __ldg((const float4*)W + (size_t)n * 128 + k4);
        uint2 lo;
        const uint2 hi = split4(v, lo);
        *(uint2*)&g_Ws[z][0][(size_t)n * DD + k4 * 4] = hi;
        *(uint2*)&g_Ws[z][1][(size_t)n * DD + k4 * 4] = lo;
    }
    if (i < 128) g_flag[i] = 64u;   // h(0) counted as published
    if (i < (int)(sizeof(g_hs) / 16))
        ((uint4*)g_hs)[i] = make_uint4(0u, 0u, 0u, 0u);
}

// ---------------- Phase 1: tensor-core GEMM 128x64, 3-stage, 2 CTA/SM --------
__global__ void __launch_bounds__(256, 2)
gemm_tc_kernel(const float* __restrict__ bi, const float* __restrict__ bc,
               const float* __restrict__ bo)
{
    extern __shared__ char smem[];
    const uint32_t sbase = (uint32_t)__cvta_generic_to_shared(smem);

    const int tid  = threadIdx.x;
    const int lane = tid & 31;
    const int warp = tid >> 5;
    const int wm = warp >> 1, wn = warp & 1;
    const int ntile = blockIdx.x, mt = blockIdx.y, z = blockIdx.z;
    const float* bia = (z == 0) ? bi : (z == 1) ? bc : bo;

    auto stage = [&](int s, int kt) {
        const int k0 = kt * 32;
        const uint32_t bufb = sbase + (uint32_t)(s * GSTAGE);
#pragma unroll
        for (int j = 0; j < 6; j++) {
            const int idx = tid + j * 256;
            const int ch = idx & 3;
            uint32_t dst;
            const __nv_bfloat16* src;
            if (idx < 1024) {
                const int spl = idx >> 9;
                const int row = (idx >> 2) & 127;
                dst = bufb + (uint32_t)(spl * 10240 + row * GSTR + ch * 16);
                src = &g_Xs[spl][(size_t)(mt * 128 + row) * DD + k0 + ch * 8];
            } else {
                const int i2 = idx - 1024;
                const int spl = i2 >> 8;
                const int row = (i2 >> 2) & 63;
                dst = bufb + (uint32_t)(20480 + spl * 5120 + row * GSTR + ch * 16);
                src = &g_Ws[z][spl][(size_t)(ntile * 64 + row) * DD + k0 + ch * 8];
            }
            cp16(dst, src);
        }
        cp_commit();
    };

    float acc[2][4][4] = {};

    stage(0, 0); stage(1, 1);

    const int rA = (lane & 7) + ((lane >> 3) & 1) * 8;
    const int cA = (lane >> 4) * 8;
    const int rB = (lane & 7) + ((lane >> 4) << 3);
    const int cB = ((lane >> 3) & 1) * 8;

    for (int kt = 0; kt < 16; kt++) {
        if (kt >= 14) cp_wait<0>(); else cp_wait<1>();
        __syncthreads();
        if (kt + 2 < 16) stage((kt + 2) % 3, kt + 2);

        const uint32_t buf = sbase + (uint32_t)((kt % 3) * GSTAGE);
        const uint32_t A1 = buf, A2 = buf + 10240;
        const uint32_t B1 = buf + 20480, B2 = buf + 25600;

#pragma unroll
        for (int k16 = 0; k16 < 2; k16++) {
            uint32_t a1[2][4], a2[2][4], b1[4][2], b2[4][2];
#pragma unroll
            for (int m2 = 0; m2 < 2; m2++) {
                const uint32_t ao =
                    (uint32_t)((wm * 32 + m2 * 16 + rA) * GSTR + (k16 * 16 + cA) * 2);
                ldsm_x4(a1[m2], A1 + ao);
                ldsm_x4(a2[m2], A2 + ao);
            }
#pragma unroll
            for (int n16 = 0; n16 < 2; n16++) {
                const uint32_t bo_ =
                    (uint32_t)((wn * 32 + n16 * 16 + rB) * GSTR + (k16 * 16 + cB) * 2);
                uint32_t r1[4], r2[4];
                ldsm_x4(r1, B1 + bo_);
                ldsm_x4(r2, B2 + bo_);
                b1[n16 * 2][0] = r1[0]; b1[n16 * 2][1] = r1[1];
                b1[n16 * 2 + 1][0] = r1[2]; b1[n16 * 2 + 1][1] = r1[3];
                b2[n16 * 2][0] = r2[0]; b2[n16 * 2][1] = r2[1];
                b2[n16 * 2 + 1][0] = r2[2]; b2[n16 * 2 + 1][1] = r2[3];
            }
#pragma unroll
            for (int m2 = 0; m2 < 2; m2++)
#pragma unroll
                for (int n8 = 0; n8 < 4; n8++) mma_bf16(acc[m2][n8], a1[m2], b1[n8]);
#pragma unroll
            for (int m2 = 0; m2 < 2; m2++)
#pragma unroll
                for (int n8 = 0; n8 < 4; n8++) mma_bf16(acc[m2][n8], a1[m2], b2[n8]);
#pragma unroll
            for (int m2 = 0; m2 < 2; m2++)
#pragma unroll
                for (int n8 = 0; n8 < 4; n8++) mma_bf16(acc[m2][n8], a2[m2], b1[n8]);
        }
    }

    __syncthreads();
    float* ep = (float*)smem;
    {
        const int gq = lane >> 2, c2 = (lane & 3) * 2;
#pragma unroll
        for (int m2 = 0; m2 < 2; m2++)
#pragma unroll
            for (int n8 = 0; n8 < 4; n8++) {
                const int m = wm * 32 + m2 * 16 + gq;
                const int n = wn * 32 + n8 * 8 + c2;
                ep[n * 132 + m]           = acc[m2][n8][0];
                ep[(n + 1) * 132 + m]     = acc[m2][n8][1];
                ep[n * 132 + m + 8]       = acc[m2][n8][2];
                ep[(n + 1) * 132 + m + 8] = acc[m2][n8][3];
            }
    }
    __syncthreads();
    {
        float* out = g_pre[z];
#pragma unroll
        for (int i = 0; i < 8; i++) {
            const int idx = tid + i * 256;
            const int oo = idx >> 5;
            const int tloc = (idx >> 4) & 1;
            const int b4 = (idx & 15) * 4;
            const float4 v = *(const float4*)&ep[oo * 132 + tloc * 64 + b4];
            const float bz = __ldg(&bia[ntile * 64 + oo]);
            float* op = out + (size_t)(mt * 2 + tloc) * (DD * BB) +
                        (size_t)(ntile * 64 + oo) * BB + b4;
            *(float4*)op = make_float4(v.x + bz, v.y + bz, v.z + bz, v.w + bz);
        }
    }
}

// ---------------- Phase 2: scan — per-thread producer poll -------------------
// Thread tid's 8 staged chunks all come from producer (tid&63)>>1: poll that
// single flag, then issue all 8 cp.async at once. One commit/wait/sync; MMA
// phases merged. Publishers release their own stores to their CTA flag.
__global__ void __launch_bounds__(256, 1)
lstm_scan_kernel(const float* __restrict__ Ui, const float* __restrict__ Uf,
                 const float* __restrict__ Uc, const float* __restrict__ Uo,
                 const float* __restrict__ bUf, const float* __restrict__ bUc,
                 const float* __restrict__ bUo,
                 float* __restrict__ outH, float* __restrict__ outC)
{
    extern __shared__ char smem[];
    const uint32_t sbase = (uint32_t)__cvta_generic_to_shared(smem);

    const int tid  = threadIdx.x;
    const int lane = tid & 31;
    const int warp = tid >> 5;
    const int kw = warp >> 2;          // k half for MMA
    const int nh = warp & 3;           // n quarter
    const int g  = blockIdx.x & 3;
    const int cig = blockIdx.x >> 2;
    const int j0 = cig * JPC;
    unsigned int* myflag = &g_flag[g * 32 + cig];
    const unsigned int* srcflag = &g_flag[g * 32 + ((tid & 63) >> 1)];

    // ---- setup: U splits into T1/T2 ------------------------------------------
    for (int idx = tid; idx < 64 * DD; idx += 256) {
        const int n = idx >> 9, k = idx & 511;
        const int gate = n >> 4, jl = n & 15;
        const float* U = (gate == 0) ? Ui : (gate == 1) ? Uf : (gate == 2) ? Uc : Uo;
        const float v = __ldg(&U[(size_t)(j0 + jl) * DD + k]);
        const __nv_bfloat16 hi = __float2bfloat16(v);
        const __nv_bfloat16 lo = __float2bfloat16(v - __bfloat162float(hi));
        *(__nv_bfloat16*)(smem + OFF_T1 + n * RSTRB + k * 2) = hi;
        *(__nv_bfloat16*)(smem + OFF_T2 + n * RSTRB + k * 2) = lo;
    }
    __syncthreads();

    uint32_t bc1[2][16][2], bc2[2][16][2];
    {
        const int brow = lane & 7;
        const int bsel = (lane >> 3) & 1;
#pragma unroll
        for (int nt = 0; nt < 2; nt++) {
            const int n0 = nh * 16 + nt * 8;
#pragma unroll
            for (int kt = 0; kt < 16; kt++) {
                const int k0 = kw * 256 + kt * 16;
                const uint32_t boff = (uint32_t)((n0 + brow) * RSTRB + (k0 + bsel * 8) * 2);
                ldsm_x2(bc1[nt][kt], sbase + OFF_T1 + boff);
                ldsm_x2(bc2[nt][kt], sbase + OFF_T2 + boff);
            }
        }
    }
    __syncthreads();   // T1/T2 rows 0..15 now reused for h staging

    const int rA = (lane & 7) + ((lane >> 3) & 1) * 8;
    const int cA = (lane >> 4) * 8;
    const uint32_t aoff = (uint32_t)(rA * RSTRB + (kw * 256 + cA) * 2);

    const int jj = tid >> 4;
    const int bb = tid & 15;
    const int jglob = j0 + jj;
    const int bglob = g * BPG + bb;
    const float bfb = __ldg(&bUf[jglob]);
    const float bcb = __ldg(&bUc[jglob]);
    const float bob = __ldg(&bUo[jglob]);

    float* P  = (float*)(smem + OFF_P);
    float* HO = (float*)(smem + OFF_HO);
    float* CO = (float*)(smem + OFF_CO);
    unsigned short* HP = (unsigned short*)(smem + OFF_HP);

    float c = 0.f;
    float xi = __ldcg(&g_pre[0][(size_t)jglob * BB + bglob]);
    float xc = __ldcg(&g_pre[1][(size_t)jglob * BB + bglob]);
    float xo = __ldcg(&g_pre[2][(size_t)jglob * BB + bglob]);

    for (int t = 0; t < TT; t++) {
        // ---- per-thread poll of MY producer, then stage all 8 chunks ---------
        {
            const unsigned tgt = 64u * (unsigned)(t + 1);
            while (ld_acq(srcflag) < tgt) { }

            const char* src = (const char*)&g_hs[g][t & 1][0][0][0];
#pragma unroll
            for (int i = 0; i < 4; i++) {          // T1
                const int m = tid + i * 256;
                const int b = m >> 6, kc = m & 63;
                cp16(sbase + OFF_T1 + b * RSTRB + kc * 16, src + (size_t)m * 16);
            }
#pragma unroll
            for (int i = 4; i < 8; i++) {          // T2
                const int m = tid + i * 256;
                const int cc = m & 1023;
                const int b = cc >> 6, kc = cc & 63;
                cp16(sbase + OFF_T2 + b * RSTRB + kc * 16,
                     src + (size_t)(BPG * DD * 2) + (size_t)cc * 16);
            }
            cp_commit();
        }

        float acc[2][4] = {};

        cp_wait<0>();
        __syncthreads();

        // ---- merged MMA: h1*U1 + h1*U2 + h2*U1 -------------------------------
#pragma unroll
        for (int kt = 0; kt < 16; kt++) {
            uint32_t a1[4], a2[4];
            const uint32_t ao = kt * 32 + aoff;
            ldsm_x4(a1, sbase + OFF_T1 + ao);
            ldsm_x4(a2, sbase + OFF_T2 + ao);
#pragma unroll
            for (int nt = 0; nt < 2; nt++) {
                mma_bf16(acc[nt], a1, bc1[nt][kt]);
                mma_bf16(acc[nt], a1, bc2[nt][kt]);
                mma_bf16(acc[nt], a2, bc1[nt][kt]);
            }
        }

        // ---- partials ---------------------------------------------------------
        {
            const int gq = lane >> 2, c2 = (lane & 3) * 2;
#pragma unroll
            for (int nt = 0; nt < 2; nt++) {
                const int n0 = nh * 16 + nt * 8 + c2;
                *(float2*)&P[(kw * 16 + gq) * PSTR + n0] =
                    make_float2(acc[nt][0], acc[nt][1]);
                *(float2*)&P[(kw * 16 + gq + 8) * PSTR + n0] =
                    make_float2(acc[nt][2], acc[nt][3]);
            }
        }
        __syncthreads();

        // ---- gates (quirks: f uses xi; i has no U-bias) -----------------------
        {
            float pre[4];
#pragma unroll
            for (int ga = 0; ga < 4; ga++) {
                const int n = ga * 16 + jj;
                pre[ga] = P[bb * PSTR + n] + P[(16 + bb) * PSTR + n];
            }
            const float pi = xi + pre[0];
            const float pf = xi + pre[1] + bfb;
            const float pc = xc + pre[2] + bcb;
            const float po = xo + pre[3] + bob;
            const float ig = sigf(pi);
            const float fg = sigf(pf);
            const float gg = tanhfast(pc);
            const float og = sigf(po);
            c = fg * c + ig * gg;
            const float h = og * tanhfast(c);

            const __nv_bfloat16 h1 = __float2bfloat16(h);
            const __nv_bfloat16 h2 = __float2bfloat16(h - __bfloat162float(h1));
            HP[0 * 256 + bb * 16 + jj] = *(const unsigned short*)&h1;
            HP[1 * 256 + bb * 16 + jj] = *(const unsigned short*)&h2;
            HO[bb * 17 + jj] = h;
            CO[bb * 17 + jj] = c;
        }
        __syncthreads();

        // ---- publish + per-thread release -------------------------------------
        if (tid < 64) {
            const int s = tid >> 5, rem = tid & 31, b = rem >> 1, part = rem & 1;
            const uint4 v = *(const uint4*)(smem + OFF_HP + s * 512 + b * 32 + part * 16);
            *(uint4*)((char*)&g_hs[g][(t + 1) & 1][s][b][j0] + part * 16) = v;
            red_release(myflag);
        }

        // ---- overlap: outputs + next-x preload --------------------------------
        {
            const int m = tid & 127;
            const int ob = m >> 3, oj = (m & 7) * 2;
            const size_t obase = (size_t)(g * BPG + ob) * (TT * DD) +
                                 (size_t)t * DD + j0 + oj;
            const float* S = (tid < 128) ? HO : CO;
            float* O = (tid < 128) ? outH : outC;
            *(float2*)&O[obase] = make_float2(S[ob * 17 + oj], S[ob * 17 + oj + 1]);
        }
        if (t + 1 < TT) {
            const size_t p2 = (size_t)(t + 1) * (DD * BB) + (size_t)jglob * BB + bglob;
            xi = __ldcg(&g_pre[0][p2]);
            xc = __ldcg(&g_pre[1][p2]);
            xo = __ldcg(&g_pre[2][p2]);
        }
    }
}

// ---------------- launch -----------------------------------------------------
extern "C" void kernel_launch(void* const* d_in, const int* in_sizes, int n_in,
                              void* d_out, int out_size) {
    const float* X   = (const float*)d_in[0];
    const float* Wi  = (const float*)d_in[1];
    const float* bi  = (const float*)d_in[2];
    // d_in[3] = Wf, d_in[4] = bf: computed-but-unused in the reference
    const float* Wc  = (const float*)d_in[5];
    const float* bc  = (const float*)d_in[6];
    const float* Wo  = (const float*)d_in[7];
    const float* bo  = (const float*)d_in[8];
    const float* Ui  = (const float*)d_in[9];
    const float* Uf  = (const float*)d_in[10];
    const float* bUf = (const float*)d_in[11];
    const float* Uc  = (const float*)d_in[12];
    const float* bUc = (const float*)d_in[13];
    const float* Uo  = (const float*)d_in[14];
    const float* bUo = (const float*)d_in[15];

    float* outH = (float*)d_out;
    float* outC = outH + (size_t)BB * TT * DD;

    split_kernel<<<(BB * TT * (DD / 4) + 255) / 256, 256>>>(X, Wi, Wc, Wo);

    cudaFuncSetAttribute(gemm_tc_kernel,
                         cudaFuncAttributeMaxDynamicSharedMemorySize, SMEM_GEMM);
    dim3 g1(DD / 64, (BB * TT) / 128, 3);
    gemm_tc_kernel<<<g1, 256, SMEM_GEMM>>>(bi, bc, bo);

    cudaFuncSetAttribute(lstm_scan_kernel,
                         cudaFuncAttributeMaxDynamicSharedMemorySize, SMEM_SCAN);
    lstm_scan_kernel<<<NG * CPG, 256, SMEM_SCAN>>>(Ui, Uf, Uc, Uo, bUf, bUc, bUo,
                                                   outH, outC);
}

// round 15
// speedup vs baseline: 1.0198x; 1.0198x over previous
#include <cuda_runtime.h>
#include <cuda_bf16.h>
#include <cstdint>
#include <cstddef>

#define BB 64
#define TT 512
#define DD 512
#define NG 4          /* batch groups */
#define CPG 32        /* CTAs per group (j split) */
#define BPG 16        /* batch columns per group */
#define JPC 16        /* j rows per CTA */

/* scan smem */
#define RSTRB 1040
#define OFF_T1 0
#define OFF_T2 66560
#define OFF_P  133120
#define OFF_HO 142080
#define OFF_CO 143168
#define OFF_HP 144256
#define SMEM_SCAN 145280

/* phase-1 tensor GEMM: tile 128m x 64n, 3-stage pipeline, 2 CTAs/SM */
#define GSTR 80
#define GSTAGE 30720
#define SMEM_GEMM 92160

#define PSTR 70

// ---------------- scratch ---------------------------------------------------
__device__ float g_pre[3][(size_t)TT * DD * BB];          // [z][t][j][b]
__device__ unsigned short g_hs[NG][2][2][BPG][DD];        // h split bf16
__device__ unsigned int g_flag[128];                      // per-CTA publish flags
__device__ __nv_bfloat16 g_Xs[2][(size_t)BB * TT * DD];
__device__ __nv_bfloat16 g_Ws[3][2][DD * DD];

// ---------------- helpers ----------------------------------------------------
__device__ __forceinline__ void cp16(uint32_t dst, const void* src) {
    asm volatile("cp.async.cg.shared.global [%0], [%1], 16;" :: "r"(dst), "l"(src));
}
__device__ __forceinline__ void cp_commit() {
    asm volatile("cp.async.commit_group;" ::: "memory");
}
template <int N> __device__ __forceinline__ void cp_wait() {
    asm volatile("cp.async.wait_group %0;" :: "n"(N) : "memory");
}
__device__ __forceinline__ void red_release(unsigned int* p) {
    asm volatile("red.release.gpu.add.u32 [%0], 1;" :: "l"(p) : "memory");
}
__device__ __forceinline__ unsigned ld_acq(const unsigned int* p) {
    unsigned v;
    asm volatile("ld.acquire.gpu.u32 %0, [%1];" : "=r"(v) : "l"(p) : "memory");
    return v;
}
__device__ __forceinline__ void ldsm_x4(uint32_t* r, uint32_t addr) {
    asm volatile("ldmatrix.sync.aligned.m8n8.x4.shared.b16 {%0,%1,%2,%3}, [%4];"
                 : "=r"(r[0]), "=r"(r[1]), "=r"(r[2]), "=r"(r[3]) : "r"(addr));
}
__device__ __forceinline__ void ldsm_x2(uint32_t* r, uint32_t addr) {
    asm volatile("ldmatrix.sync.aligned.m8n8.x2.shared.b16 {%0,%1}, [%2];"
                 : "=r"(r[0]), "=r"(r[1]) : "r"(addr));
}
__device__ __forceinline__ void mma_bf16(float* d, const uint32_t* a, const uint32_t* b) {
    asm volatile(
        "mma.sync.aligned.m16n8k16.row.col.f32.bf16.bf16.f32 "
        "{%0,%1,%2,%3},{%4,%5,%6,%7},{%8,%9},{%0,%1,%2,%3};"
        : "+f"(d[0]), "+f"(d[1]), "+f"(d[2]), "+f"(d[3])
        : "r"(a[0]), "r"(a[1]), "r"(a[2]), "r"(a[3]), "r"(b[0]), "r"(b[1]));
}
__device__ __forceinline__ uint2 split4(float4 v, uint2& lo) {
    __nv_bfloat16 h0 = __float2bfloat16(v.x), h1 = __float2bfloat16(v.y);
    __nv_bfloat16 h2 = __float2bfloat16(v.z), h3 = __float2bfloat16(v.w);
    __nv_bfloat16 l0 = __float2bfloat16(v.x - __bfloat162float(h0));
    __nv_bfloat16 l1 = __float2bfloat16(v.y - __bfloat162float(h1));
    __nv_bfloat16 l2 = __float2bfloat16(v.z - __bfloat162float(h2));
    __nv_bfloat16 l3 = __float2bfloat16(v.w - __bfloat162float(h3));
    __nv_bfloat162 hp0{h0, h1}, hp1{h2, h3}, lp0{l0, l1}, lp1{l2, l3};
    uint2 hi;
    hi.x = *(unsigned*)&hp0; hi.y = *(unsigned*)&hp1;
    lo.x = *(unsigned*)&lp0; lo.y = *(unsigned*)&lp1;
    return hi;
}
__device__ __forceinline__ float sigf(float x) {
    return __fdividef(1.f, 1.f + __expf(-x));
}
__device__ __forceinline__ float tanhfast(float x) {
    const float a = fabsf(x);
    const float e = __expf(2.f * a);
    const float r = 1.f - __fdividef(2.f, e + 1.f);
    return copysignf(r, x);
}

// ---------------- Phase 0: split X/W into bf16 hi/lo, init scan state --------
__global__ void __launch_bounds__(256)
split_kernel(const float* __restrict__ X, const float* __restrict__ Wi,
             const float* __restrict__ Wc, const float* __restrict__ Wo)
{
    const int i = blockIdx.x * 256 + threadIdx.x;
    if (i < BB * TT * (DD / 4)) {
        const int m = i >> 7, k4 = i & 127;
        const int b = m & 63, t = m >> 6;
        const float4 v = __ldg((const float4*)X + ((size_t)b * TT + t) * 128 + k4);
        uint2 lo;
        const uint2 hi = split4(v, lo);
        *(uint2*)&g_Xs[0][(size_t)m * DD + k4 * 4] = hi;
        *(uint2*)&g_Xs[1][(size_t)m * DD + k4 * 4] = lo;
    }
    if (i < 3 * DD * (DD / 4)) {
        const int z = i / (DD * 128);
        const int r = i - z * (DD * 128);
        const int n = r >> 7, k4 = r & 127;
        const float* W = (z == 0) ? Wi : (z == 1) ? Wc : Wo;
        const float4 v = __ldg((const float4*)W + (size_t)n * 128 + k4);
        uint2 lo;
        const uint2 hi = split4(v, lo);
        *(uint2*)&g_Ws[z][0][(size_t)n * DD + k4 * 4] = hi;
        *(uint2*)&g_Ws[z][1][(size_t)n * DD + k4 * 4] = lo;
    }
    if (i < 128) g_flag[i] = 64u;   // h(0) counted as published
    if (i < (int)(sizeof(g_hs) / 16))
        ((uint4*)g_hs)[i] = make_uint4(0u, 0u, 0u, 0u);
}

// ---------------- Phase 1: tensor-core GEMM 128x64, 3-stage, 2 CTA/SM --------
__global__ void __launch_bounds__(256, 2)
gemm_tc_kernel(const float* __restrict__ bi, const float* __restrict__ bc,
               const float* __restrict__ bo)
{
    extern __shared__ char smem[];
    const uint32_t sbase = (uint32_t)__cvta_generic_to_shared(smem);

    const int tid  = threadIdx.x;
    const int lane = tid & 31;
    const int warp = tid >> 5;
    const int wm = warp >> 1, wn = warp & 1;
    const int ntile = blockIdx.x, mt = blockIdx.y, z = blockIdx.z;
    const float* bia = (z == 0) ? bi : (z == 1) ? bc : bo;

    auto stage = [&](int s, int kt) {
        const int k0 = kt * 32;
        const uint32_t bufb = sbase + (uint32_t)(s * GSTAGE);
#pragma unroll
        for (int j = 0; j < 6; j++) {
            const int idx = tid + j * 256;
            const int ch = idx & 3;
            uint32_t dst;
            const __nv_bfloat16* src;
            if (idx < 1024) {
                const int spl = idx >> 9;
                const int row = (idx >> 2) & 127;
                dst = bufb + (uint32_t)(spl * 10240 + row * GSTR + ch * 16);
                src = &g_Xs[spl][(size_t)(mt * 128 + row) * DD + k0 + ch * 8];
            } else {
                const int i2 = idx - 1024;
                const int spl = i2 >> 8;
                const int row = (i2 >> 2) & 63;
                dst = bufb + (uint32_t)(20480 + spl * 5120 + row * GSTR + ch * 16);
                src = &g_Ws[z][spl][(size_t)(ntile * 64 + row) * DD + k0 + ch * 8];
            }
            cp16(dst, src);
        }
        cp_commit();
    };

    float acc[2][4][4] = {};

    stage(0, 0); stage(1, 1);

    const int rA = (lane & 7) + ((lane >> 3) & 1) * 8;
    const int cA = (lane >> 4) * 8;
    const int rB = (lane & 7) + ((lane >> 4) << 3);
    const int cB = ((lane >> 3) & 1) * 8;

    for (int kt = 0; kt < 16; kt++) {
        if (kt >= 14) cp_wait<0>(); else cp_wait<1>();
        __syncthreads();
        if (kt + 2 < 16) stage((kt + 2) % 3, kt + 2);

        const uint32_t buf = sbase + (uint32_t)((kt % 3) * GSTAGE);
        const uint32_t A1 = buf, A2 = buf + 10240;
        const uint32_t B1 = buf + 20480, B2 = buf + 25600;

#pragma unroll
        for (int k16 = 0; k16 < 2; k16++) {
            uint32_t a1[2][4], a2[2][4], b1[4][2], b2[4][2];
#pragma unroll
            for (int m2 = 0; m2 < 2; m2++) {
                const uint32_t ao =
                    (uint32_t)((wm * 32 + m2 * 16 + rA) * GSTR + (k16 * 16 + cA) * 2);
                ldsm_x4(a1[m2], A1 + ao);
                ldsm_x4(a2[m2], A2 + ao);
            }
#pragma unroll
            for (int n16 = 0; n16 < 2; n16++) {
                const uint32_t bo_ =
                    (uint32_t)((wn * 32 + n16 * 16 + rB) * GSTR + (k16 * 16 + cB) * 2);
                uint32_t r1[4], r2[4];
                ldsm_x4(r1, B1 + bo_);
                ldsm_x4(r2, B2 + bo_);
                b1[n16 * 2][0] = r1[0]; b1[n16 * 2][1] = r1[1];
                b1[n16 * 2 + 1][0] = r1[2]; b1[n16 * 2 + 1][1] = r1[3];
                b2[n16 * 2][0] = r2[0]; b2[n16 * 2][1] = r2[1];
                b2[n16 * 2 + 1][0] = r2[2]; b2[n16 * 2 + 1][1] = r2[3];
            }
#pragma unroll
            for (int m2 = 0; m2 < 2; m2++)
#pragma unroll
                for (int n8 = 0; n8 < 4; n8++) mma_bf16(acc[m2][n8], a1[m2], b1[n8]);
#pragma unroll
            for (int m2 = 0; m2 < 2; m2++)
#pragma unroll
                for (int n8 = 0; n8 < 4; n8++) mma_bf16(acc[m2][n8], a1[m2], b2[n8]);
#pragma unroll
            for (int m2 = 0; m2 < 2; m2++)
#pragma unroll
                for (int n8 = 0; n8 < 4; n8++) mma_bf16(acc[m2][n8], a2[m2], b1[n8]);
        }
    }

    __syncthreads();
    float* ep = (float*)smem;
    {
        const int gq = lane >> 2, c2 = (lane & 3) * 2;
#pragma unroll
        for (int m2 = 0; m2 < 2; m2++)
#pragma unroll
            for (int n8 = 0; n8 < 4; n8++) {
                const int m = wm * 32 + m2 * 16 + gq;
                const int n = wn * 32 + n8 * 8 + c2;
                ep[n * 132 + m]           = acc[m2][n8][0];
                ep[(n + 1) * 132 + m]     = acc[m2][n8][1];
                ep[n * 132 + m + 8]       = acc[m2][n8][2];
                ep[(n + 1) * 132 + m + 8] = acc[m2][n8][3];
            }
    }
    __syncthreads();
    {
        float* out = g_pre[z];
#pragma unroll
        for (int i = 0; i < 8; i++) {
            const int idx = tid + i * 256;
            const int oo = idx >> 5;
            const int tloc = (idx >> 4) & 1;
            const int b4 = (idx & 15) * 4;
            const float4 v = *(const float4*)&ep[oo * 132 + tloc * 64 + b4];
            const float bz = __ldg(&bia[ntile * 64 + oo]);
            float* op = out + (size_t)(mt * 2 + tloc) * (DD * BB) +
                        (size_t)(ntile * 64 + oo) * BB + b4;
            *(float4*)op = make_float4(v.x + bz, v.y + bz, v.z + bz, v.w + bz);
        }
    }
}

// ---------------- Phase 2: scan — R13 structure + per-thread producer poll ---
// Thread tid's chunks all come from producer (tid&63)>>1: poll ONE flag, then
// stage T1 (commit) and T2 (commit) separately so phase-A MMA overlaps T2's
// L2 fetch. Publishers release their own stores to their CTA flag.
__global__ void __launch_bounds__(256, 1)
lstm_scan_kernel(const float* __restrict__ Ui, const float* __restrict__ Uf,
                 const float* __restrict__ Uc, const float* __restrict__ Uo,
                 const float* __restrict__ bUf, const float* __restrict__ bUc,
                 const float* __restrict__ bUo,
                 float* __restrict__ outH, float* __restrict__ outC)
{
    extern __shared__ char smem[];
    const uint32_t sbase = (uint32_t)__cvta_generic_to_shared(smem);

    const int tid  = threadIdx.x;
    const int lane = tid & 31;
    const int warp = tid >> 5;
    const int kw = warp >> 2;          // k half for MMA
    const int nh = warp & 3;           // n quarter
    const int g  = blockIdx.x & 3;
    const int cig = blockIdx.x >> 2;
    const int j0 = cig * JPC;
    unsigned int* myflag = &g_flag[g * 32 + cig];
    const unsigned int* srcflag = &g_flag[g * 32 + ((tid & 63) >> 1)];

    // ---- setup: U splits into T1/T2 ------------------------------------------
    for (int idx = tid; idx < 64 * DD; idx += 256) {
        const int n = idx >> 9, k = idx & 511;
        const int gate = n >> 4, jl = n & 15;
        const float* U = (gate == 0) ? Ui : (gate == 1) ? Uf : (gate == 2) ? Uc : Uo;
        const float v = __ldg(&U[(size_t)(j0 + jl) * DD + k]);
        const __nv_bfloat16 hi = __float2bfloat16(v);
        const __nv_bfloat16 lo = __float2bfloat16(v - __bfloat162float(hi));
        *(__nv_bfloat16*)(smem + OFF_T1 + n * RSTRB + k * 2) = hi;
        *(__nv_bfloat16*)(smem + OFF_T2 + n * RSTRB + k * 2) = lo;
    }
    __syncthreads();

    uint32_t bc1[2][16][2], bc2[2][16][2];
    {
        const int brow = lane & 7;
        const int bsel = (lane >> 3) & 1;
#pragma unroll
        for (int nt = 0; nt < 2; nt++) {
            const int n0 = nh * 16 + nt * 8;
#pragma unroll
            for (int kt = 0; kt < 16; kt++) {
                const int k0 = kw * 256 + kt * 16;
                const uint32_t boff = (uint32_t)((n0 + brow) * RSTRB + (k0 + bsel * 8) * 2);
                ldsm_x2(bc1[nt][kt], sbase + OFF_T1 + boff);
                ldsm_x2(bc2[nt][kt], sbase + OFF_T2 + boff);
            }
        }
    }
    __syncthreads();   // T1/T2 rows 0..15 now reused for h staging

    const int rA = (lane & 7) + ((lane >> 3) & 1) * 8;
    const int cA = (lane >> 4) * 8;
    const uint32_t aoff = (uint32_t)(rA * RSTRB + (kw * 256 + cA) * 2);

    const int jj = tid >> 4;
    const int bb = tid & 15;
    const int jglob = j0 + jj;
    const int bglob = g * BPG + bb;
    const float bfb = __ldg(&bUf[jglob]);
    const float bcb = __ldg(&bUc[jglob]);
    const float bob = __ldg(&bUo[jglob]);

    float* P  = (float*)(smem + OFF_P);
    float* HO = (float*)(smem + OFF_HO);
    float* CO = (float*)(smem + OFF_CO);
    unsigned short* HP = (unsigned short*)(smem + OFF_HP);

    float c = 0.f;
    float xi = __ldcg(&g_pre[0][(size_t)jglob * BB + bglob]);
    float xc = __ldcg(&g_pre[1][(size_t)jglob * BB + bglob]);
    float xo = __ldcg(&g_pre[2][(size_t)jglob * BB + bglob]);

    for (int t = 0; t < TT; t++) {
        // ---- per-thread poll of MY single producer flag ----------------------
        {
            const unsigned tgt = 64u * (unsigned)(t + 1);
            while (ld_acq(srcflag) < tgt) { }
        }

        // ---- stage T1 (commit), then T2 (commit) — keep fetch/MMA overlap ----
        {
            const char* src = (const char*)&g_hs[g][t & 1][0][0][0];
#pragma unroll
            for (int i = 0; i < 4; i++) {          // T1
                const int m = tid + i * 256;
                const int b = m >> 6, kc = m & 63;
                cp16(sbase + OFF_T1 + b * RSTRB + kc * 16, src + (size_t)m * 16);
            }
            cp_commit();
#pragma unroll
            for (int i = 4; i < 8; i++) {          // T2
                const int m = tid + i * 256;
                const int cc = m & 1023;
                const int b = cc >> 6, kc = cc & 63;
                cp16(sbase + OFF_T2 + b * RSTRB + kc * 16,
                     src + (size_t)(BPG * DD * 2) + (size_t)cc * 16);
            }
            cp_commit();
        }

        float acc[2][4] = {};

        cp_wait<1>();
        __syncthreads();
        // ---- phase A: h1*U1 + h1*U2 (T1 only; T2 still in flight) ------------
#pragma unroll
        for (int kt = 0; kt < 16; kt++) {
            uint32_t a1[4];
            ldsm_x4(a1, sbase + OFF_T1 + kt * 32 + aoff);
#pragma unroll
            for (int nt = 0; nt < 2; nt++) {
                mma_bf16(acc[nt], a1, bc1[nt][kt]);
                mma_bf16(acc[nt], a1, bc2[nt][kt]);
            }
        }
        cp_wait<0>();
        __syncthreads();
        // ---- phase B: h2*U1 ---------------------------------------------------
#pragma unroll
        for (int kt = 0; kt < 16; kt++) {
            uint32_t a2[4];
            ldsm_x4(a2, sbase + OFF_T2 + kt * 32 + aoff);
#pragma unroll
            for (int nt = 0; nt < 2; nt++)
                mma_bf16(acc[nt], a2, bc1[nt][kt]);
        }

        // ---- partials ---------------------------------------------------------
        {
            const int gq = lane >> 2, c2 = (lane & 3) * 2;
#pragma unroll
            for (int nt = 0; nt < 2; nt++) {
                const int n0 = nh * 16 + nt * 8 + c2;
                *(float2*)&P[(kw * 16 + gq) * PSTR + n0] =
                    make_float2(acc[nt][0], acc[nt][1]);
                *(float2*)&P[(kw * 16 + gq + 8) * PSTR + n0] =
                    make_float2(acc[nt][2], acc[nt][3]);
            }
        }
        __syncthreads();

        // ---- gates (quirks: f uses xi; i has no U-bias) -----------------------
        {
            float pre[4];
#pragma unroll
            for (int ga = 0; ga < 4; ga++) {
                const int n = ga * 16 + jj;
                pre[ga] = P[bb * PSTR + n] + P[(16 + bb) * PSTR + n];
            }
            const float pi = xi + pre[0];
            const float pf = xi + pre[1] + bfb;
            const float pc = xc + pre[2] + bcb;
            const float po = xo + pre[3] + bob;
            const float ig = sigf(pi);
            const float fg = sigf(pf);
            const float gg = tanhfast(pc);
            const float og = sigf(po);
            c = fg * c + ig * gg;
            const float h = og * tanhfast(c);

            const __nv_bfloat16 h1 = __float2bfloat16(h);
            const __nv_bfloat16 h2 = __float2bfloat16(h - __bfloat162float(h1));
            HP[0 * 256 + bb * 16 + jj] = *(const unsigned short*)&h1;
            HP[1 * 256 + bb * 16 + jj] = *(const unsigned short*)&h2;
            HO[bb * 17 + jj] = h;
            CO[bb * 17 + jj] = c;
        }
        __syncthreads();

        // ---- publish + per-thread release -------------------------------------
        if (tid < 64) {
            const int s = tid >> 5, rem = tid & 31, b = rem >> 1, part = rem & 1;
            const uint4 v = *(const uint4*)(smem + OFF_HP + s * 512 + b * 32 + part * 16);
            *(uint4*)((char*)&g_hs[g][(t + 1) & 1][s][b][j0] + part * 16) = v;
            red_release(myflag);
        }

        // ---- overlap: outputs + next-x preload --------------------------------
        {
            const int m = tid & 127;
            const int ob = m >> 3, oj = (m & 7) * 2;
            const size_t obase = (size_t)(g * BPG + ob) * (TT * DD) +
                                 (size_t)t * DD + j0 + oj;
            const float* S = (tid < 128) ? HO : CO;
            float* O = (tid < 128) ? outH : outC;
            *(float2*)&O[obase] = make_float2(S[ob * 17 + oj], S[ob * 17 + oj + 1]);
        }
        if (t + 1 < TT) {
            const size_t p2 = (size_t)(t + 1) * (DD * BB) + (size_t)jglob * BB + bglob;
            xi = __ldcg(&g_pre[0][p2]);
            xc = __ldcg(&g_pre[1][p2]);
            xo = __ldcg(&g_pre[2][p2]);
        }
    }
}

// ---------------- launch -----------------------------------------------------
extern "C" void kernel_launch(void* const* d_in, const int* in_sizes, int n_in,
                              void* d_out, int out_size) {
    const float* X   = (const float*)d_in[0];
    const float* Wi  = (const float*)d_in[1];
    const float* bi  = (const float*)d_in[2];
    // d_in[3] = Wf, d_in[4] = bf: computed-but-unused in the reference
    const float* Wc  = (const float*)d_in[5];
    const float* bc  = (const float*)d_in[6];
    const float* Wo  = (const float*)d_in[7];
    const float* bo  = (const float*)d_in[8];
    const float* Ui  = (const float*)d_in[9];
    const float* Uf  = (const float*)d_in[10];
    const float* bUf = (const float*)d_in[11];
    const float* Uc  = (const float*)d_in[12];
    const float* bUc = (const float*)d_in[13];
    const float* Uo  = (const float*)d_in[14];
    const float* bUo = (const float*)d_in[15];

    float* outH = (float*)d_out;
    float* outC = outH + (size_t)BB * TT * DD;

    split_kernel<<<(BB * TT * (DD / 4) + 255) / 256, 256>>>(X, Wi, Wc, Wo);

    cudaFuncSetAttribute(gemm_tc_kernel,
                         cudaFuncAttributeMaxDynamicSharedMemorySize, SMEM_GEMM);
    dim3 g1(DD / 64, (BB * TT) / 128, 3);
    gemm_tc_kernel<<<g1, 256, SMEM_GEMM>>>(bi, bc, bo);

    cudaFuncSetAttribute(lstm_scan_kernel,
                         cudaFuncAttributeMaxDynamicSharedMemorySize, SMEM_SCAN);
    lstm_scan_kernel<<<NG * CPG, 256, SMEM_SCAN>>>(Ui, Uf, Uc, Uo, bUf, bUc, bUo,
                                                   outH, outC);
}

// round 16
// speedup vs baseline: 1.0316x; 1.0116x over previous
#include <cuda_runtime.h>
#include <cuda_bf16.h>
#include <cstdint>
#include <cstddef>

#define BB 64
#define TT 512
#define DD 512
#define NG 4          /* batch groups */
#define CPG 32        /* CTAs per group (j split) */
#define BPG 16        /* batch columns per group */
#define JPC 16        /* j rows per CTA */

/* scan smem */
#define RSTRB 1040
#define OFF_T1 0
#define OFF_T2 66560
#define OFF_P  133120
#define OFF_HO 142080
#define OFF_CO 143168
#define OFF_HP 144256
#define SMEM_SCAN 145280

/* phase-1 tensor GEMM: tile 128m x 64n, 3-stage pipeline, 2 CTAs/SM */
#define GSTR 80
#define GSTAGE 30720
#define SMEM_GEMM 92160

#define PSTR 70

// ---------------- scratch ---------------------------------------------------
__device__ float g_pre[3][(size_t)TT * DD * BB];          // [z][t][j][b]
__device__ unsigned short g_hs[NG][2][2][BPG][DD];        // h split bf16
__device__ unsigned int g_flag[128];                      // per-CTA publish flags
__device__ __nv_bfloat16 g_Xs[2][(size_t)BB * TT * DD];
__device__ __nv_bfloat16 g_Ws[3][2][DD * DD];

// ---------------- helpers ----------------------------------------------------
__device__ __forceinline__ void cp16(uint32_t dst, const void* src) {
    asm volatile("cp.async.cg.shared.global [%0], [%1], 16;" :: "r"(dst), "l"(src));
}
__device__ __forceinline__ void cp_commit() {
    asm volatile("cp.async.commit_group;" ::: "memory");
}
template <int N> __device__ __forceinline__ void cp_wait() {
    asm volatile("cp.async.wait_group %0;" :: "n"(N) : "memory");
}
__device__ __forceinline__ void red_release(unsigned int* p) {
    asm volatile("red.release.gpu.add.u32 [%0], 1;" :: "l"(p) : "memory");
}
__device__ __forceinline__ unsigned ld_acq(const unsigned int* p) {
    unsigned v;
    asm volatile("ld.acquire.gpu.u32 %0, [%1];" : "=r"(v) : "l"(p) : "memory");
    return v;
}
__device__ __forceinline__ void ldsm_x4(uint32_t* r, uint32_t addr) {
    asm volatile("ldmatrix.sync.aligned.m8n8.x4.shared.b16 {%0,%1,%2,%3}, [%4];"
                 : "=r"(r[0]), "=r"(r[1]), "=r"(r[2]), "=r"(r[3]) : "r"(addr));
}
__device__ __forceinline__ void ldsm_x2(uint32_t* r, uint32_t addr) {
    asm volatile("ldmatrix.sync.aligned.m8n8.x2.shared.b16 {%0,%1}, [%2];"
                 : "=r"(r[0]), "=r"(r[1]) : "r"(addr));
}
__device__ __forceinline__ void mma_bf16(float* d, const uint32_t* a, const uint32_t* b) {
    asm volatile(
        "mma.sync.aligned.m16n8k16.row.col.f32.bf16.bf16.f32 "
        "{%0,%1,%2,%3},{%4,%5,%6,%7},{%8,%9},{%0,%1,%2,%3};"
        : "+f"(d[0]), "+f"(d[1]), "+f"(d[2]), "+f"(d[3])
        : "r"(a[0]), "r"(a[1]), "r"(a[2]), "r"(a[3]), "r"(b[0]), "r"(b[1]));
}
__device__ __forceinline__ uint2 split4(float4 v, uint2& lo) {
    __nv_bfloat16 h0 = __float2bfloat16(v.x), h1 = __float2bfloat16(v.y);
    __nv_bfloat16 h2 = __float2bfloat16(v.z), h3 = __float2bfloat16(v.w);
    __nv_bfloat16 l0 = __float2bfloat16(v.x - __bfloat162float(h0));
    __nv_bfloat16 l1 = __float2bfloat16(v.y - __bfloat162float(h1));
    __nv_bfloat16 l2 = __float2bfloat16(v.z - __bfloat162float(h2));
    __nv_bfloat16 l3 = __float2bfloat16(v.w - __bfloat162float(h3));
    __nv_bfloat162 hp0{h0, h1}, hp1{h2, h3}, lp0{l0, l1}, lp1{l2, l3};
    uint2 hi;
    hi.x = *(unsigned*)&hp0; hi.y = *(unsigned*)&hp1;
    lo.x = *(unsigned*)&lp0; lo.y = *(unsigned*)&lp1;
    return hi;
}
__device__ __forceinline__ float sigf(float x) {
    return __fdividef(1.f, 1.f + __expf(-x));
}
__device__ __forceinline__ float tanhfast(float x) {
    const float a = fabsf(x);
    const float e = __expf(2.f * a);
    const float r = 1.f - __fdividef(2.f, e + 1.f);
    return copysignf(r, x);
}

// ---------------- Phase -1: dummy (steers ncu capture slot onto the scan) ----
// Also absorbs scan-state init (flags + h buffer zeroing).
__global__ void __launch_bounds__(256)
dummy_init_kernel() {
    const int i = blockIdx.x * 256 + threadIdx.x;
    if (i < 128) g_flag[i] = 64u;   // h(0) counted as published
    if (i < (int)(sizeof(g_hs) / 16))
        ((uint4*)g_hs)[i] = make_uint4(0u, 0u, 0u, 0u);
}

// ---------------- Phase 0: split X/W into bf16 hi/lo --------------------------
__global__ void __launch_bounds__(256)
split_kernel(const float* __restrict__ X, const float* __restrict__ Wi,
             const float* __restrict__ Wc, const float* __restrict__ Wo)
{
    const int i = blockIdx.x * 256 + threadIdx.x;
    if (i < BB * TT * (DD / 4)) {
        const int m = i >> 7, k4 = i & 127;
        const int b = m & 63, t = m >> 6;
        const float4 v = __ldg((const float4*)X + ((size_t)b * TT + t) * 128 + k4);
        uint2 lo;
        const uint2 hi = split4(v, lo);
        *(uint2*)&g_Xs[0][(size_t)m * DD + k4 * 4] = hi;
        *(uint2*)&g_Xs[1][(size_t)m * DD + k4 * 4] = lo;
    }
    if (i < 3 * DD * (DD / 4)) {
        const int z = i / (DD * 128);
        const int r = i - z * (DD * 128);
        const int n = r >> 7, k4 = r & 127;
        const float* W = (z == 0) ? Wi : (z == 1) ? Wc : Wo;
        const float4 v = __ldg((const float4*)W + (size_t)n * 128 + k4);
        uint2 lo;
        const uint2 hi = split4(v, lo);
        *(uint2*)&g_Ws[z][0][(size_t)n * DD + k4 * 4] = hi;
        *(uint2*)&g_Ws[z][1][(size_t)n * DD + k4 * 4] = lo;
    }
}

// ---------------- Phase 1: tensor-core GEMM 128x64, 3-stage, 2 CTA/SM --------
__global__ void __launch_bounds__(256, 2)
gemm_tc_kernel(const float* __restrict__ bi, const float* __restrict__ bc,
               const float* __restrict__ bo)
{
    extern __shared__ char smem[];
    const uint32_t sbase = (uint32_t)__cvta_generic_to_shared(smem);

    const int tid  = threadIdx.x;
    const int lane = tid & 31;
    const int warp = tid >> 5;
    const int wm = warp >> 1, wn = warp & 1;
    const int ntile = blockIdx.x, mt = blockIdx.y, z = blockIdx.z;
    const float* bia = (z == 0) ? bi : (z == 1) ? bc : bo;

    auto stage = [&](int s, int kt) {
        const int k0 = kt * 32;
        const uint32_t bufb = sbase + (uint32_t)(s * GSTAGE);
#pragma unroll
        for (int j = 0; j < 6; j++) {
            const int idx = tid + j * 256;
            const int ch = idx & 3;
            uint32_t dst;
            const __nv_bfloat16* src;
            if (idx < 1024) {
                const int spl = idx >> 9;
                const int row = (idx >> 2) & 127;
                dst = bufb + (uint32_t)(spl * 10240 + row * GSTR + ch * 16);
                src = &g_Xs[spl][(size_t)(mt * 128 + row) * DD + k0 + ch * 8];
            } else {
                const int i2 = idx - 1024;
                const int spl = i2 >> 8;
                const int row = (i2 >> 2) & 63;
                dst = bufb + (uint32_t)(20480 + spl * 5120 + row * GSTR + ch * 16);
                src = &g_Ws[z][spl][(size_t)(ntile * 64 + row) * DD + k0 + ch * 8];
            }
            cp16(dst, src);
        }
        cp_commit();
    };

    float acc[2][4][4] = {};

    stage(0, 0); stage(1, 1);

    const int rA = (lane & 7) + ((lane >> 3) & 1) * 8;
    const int cA = (lane >> 4) * 8;
    const int rB = (lane & 7) + ((lane >> 4) << 3);
    const int cB = ((lane >> 3) & 1) * 8;

    for (int kt = 0; kt < 16; kt++) {
        if (kt >= 14) cp_wait<0>(); else cp_wait<1>();
        __syncthreads();
        if (kt + 2 < 16) stage((kt + 2) % 3, kt + 2);

        const uint32_t buf = sbase + (uint32_t)((kt % 3) * GSTAGE);
        const uint32_t A1 = buf, A2 = buf + 10240;
        const uint32_t B1 = buf + 20480, B2 = buf + 25600;

#pragma unroll
        for (int k16 = 0; k16 < 2; k16++) {
            uint32_t a1[2][4], a2[2][4], b1[4][2], b2[4][2];
#pragma unroll
            for (int m2 = 0; m2 < 2; m2++) {
                const uint32_t ao =
                    (uint32_t)((wm * 32 + m2 * 16 + rA) * GSTR + (k16 * 16 + cA) * 2);
                ldsm_x4(a1[m2], A1 + ao);
                ldsm_x4(a2[m2], A2 + ao);
            }
#pragma unroll
            for (int n16 = 0; n16 < 2; n16++) {
                const uint32_t bo_ =
                    (uint32_t)((wn * 32 + n16 * 16 + rB) * GSTR + (k16 * 16 + cB) * 2);
                uint32_t r1[4], r2[4];
                ldsm_x4(r1, B1 + bo_);
                ldsm_x4(r2, B2 + bo_);
                b1[n16 * 2][0] = r1[0]; b1[n16 * 2][1] = r1[1];
                b1[n16 * 2 + 1][0] = r1[2]; b1[n16 * 2 + 1][1] = r1[3];
                b2[n16 * 2][0] = r2[0]; b2[n16 * 2][1] = r2[1];
                b2[n16 * 2 + 1][0] = r2[2]; b2[n16 * 2 + 1][1] = r2[3];
            }
#pragma unroll
            for (int m2 = 0; m2 < 2; m2++)
#pragma unroll
                for (int n8 = 0; n8 < 4; n8++) mma_bf16(acc[m2][n8], a1[m2], b1[n8]);
#pragma unroll
            for (int m2 = 0; m2 < 2; m2++)
#pragma unroll
                for (int n8 = 0; n8 < 4; n8++) mma_bf16(acc[m2][n8], a1[m2], b2[n8]);
#pragma unroll
            for (int m2 = 0; m2 < 2; m2++)
#pragma unroll
                for (int n8 = 0; n8 < 4; n8++) mma_bf16(acc[m2][n8], a2[m2], b1[n8]);
        }
    }

    __syncthreads();
    float* ep = (float*)smem;
    {
        const int gq = lane >> 2, c2 = (lane & 3) * 2;
#pragma unroll
        for (int m2 = 0; m2 < 2; m2++)
#pragma unroll
            for (int n8 = 0; n8 < 4; n8++) {
                const int m = wm * 32 + m2 * 16 + gq;
                const int n = wn * 32 + n8 * 8 + c2;
                ep[n * 132 + m]           = acc[m2][n8][0];
                ep[(n + 1) * 132 + m]     = acc[m2][n8][1];
                ep[n * 132 + m + 8]       = acc[m2][n8][2];
                ep[(n + 1) * 132 + m + 8] = acc[m2][n8][3];
            }
    }
    __syncthreads();
    {
        float* out = g_pre[z];
#pragma unroll
        for (int i = 0; i < 8; i++) {
            const int idx = tid + i * 256;
            const int oo = idx >> 5;
            const int tloc = (idx >> 4) & 1;
            const int b4 = (idx & 15) * 4;
            const float4 v = *(const float4*)&ep[oo * 132 + tloc * 64 + b4];
            const float bz = __ldg(&bia[ntile * 64 + oo]);
            float* op = out + (size_t)(mt * 2 + tloc) * (DD * BB) +
                        (size_t)(ntile * 64 + oo) * BB + b4;
            *(float4*)op = make_float4(v.x + bz, v.y + bz, v.z + bz, v.w + bz);
        }
    }
}

// ---------------- Phase 2: scan (R13 structure — best known) -----------------
// Warp w polls the 16 producer flags its staging half depends on; publishers
// release their own stores to their CTA flag. Two-phase MMA keeps T2 fetch
// overlapped with phase-A compute.
__global__ void __launch_bounds__(256, 1)
lstm_scan_kernel(const float* __restrict__ Ui, const float* __restrict__ Uf,
                 const float* __restrict__ Uc, const float* __restrict__ Uo,
                 const float* __restrict__ bUf, const float* __restrict__ bUc,
                 const float* __restrict__ bUo,
                 float* __restrict__ outH, float* __restrict__ outC)
{
    extern __shared__ char smem[];
    const uint32_t sbase = (uint32_t)__cvta_generic_to_shared(smem);

    const int tid  = threadIdx.x;
    const int lane = tid & 31;
    const int warp = tid >> 5;
    const int kw = warp >> 2;          // k half for MMA
    const int nh = warp & 3;           // n quarter
    const int g  = blockIdx.x & 3;
    const int cig = blockIdx.x >> 2;
    const int j0 = cig * JPC;
    unsigned int* myflag = &g_flag[g * 32 + cig];
    const int half = warp & 1;         // staging producer half

    // ---- setup: U splits into T1/T2 ------------------------------------------
    for (int idx = tid; idx < 64 * DD; idx += 256) {
        const int n = idx >> 9, k = idx & 511;
        const int gate = n >> 4, jl = n & 15;
        const float* U = (gate == 0) ? Ui : (gate == 1) ? Uf : (gate == 2) ? Uc : Uo;
        const float v = __ldg(&U[(size_t)(j0 + jl) * DD + k]);
        const __nv_bfloat16 hi = __float2bfloat16(v);
        const __nv_bfloat16 lo = __float2bfloat16(v - __bfloat162float(hi));
        *(__nv_bfloat16*)(smem + OFF_T1 + n * RSTRB + k * 2) = hi;
        *(__nv_bfloat16*)(smem + OFF_T2 + n * RSTRB + k * 2) = lo;
    }
    __syncthreads();

    uint32_t bc1[2][16][2], bc2[2][16][2];
    {
        const int brow = lane & 7;
        const int bsel = (lane >> 3) & 1;
#pragma unroll
        for (int nt = 0; nt < 2; nt++) {
            const int n0 = nh * 16 + nt * 8;
#pragma unroll
            for (int kt = 0; kt < 16; kt++) {
                const int k0 = kw * 256 + kt * 16;
                const uint32_t boff = (uint32_t)((n0 + brow) * RSTRB + (k0 + bsel * 8) * 2);
                ldsm_x2(bc1[nt][kt], sbase + OFF_T1 + boff);
                ldsm_x2(bc2[nt][kt], sbase + OFF_T2 + boff);
            }
        }
    }
    __syncthreads();   // T1/T2 rows 0..15 now reused for h staging

    const int rA = (lane & 7) + ((lane >> 3) & 1) * 8;
    const int cA = (lane >> 4) * 8;
    const uint32_t aoff = (uint32_t)(rA * RSTRB + (kw * 256 + cA) * 2);

    const int jj = tid >> 4;
    const int bb = tid & 15;
    const int jglob = j0 + jj;
    const int bglob = g * BPG + bb;
    const float bfb = __ldg(&bUf[jglob]);
    const float bcb = __ldg(&bUc[jglob]);
    const float bob = __ldg(&bUo[jglob]);

    float* P  = (float*)(smem + OFF_P);
    float* HO = (float*)(smem + OFF_HO);
    float* CO = (float*)(smem + OFF_CO);
    unsigned short* HP = (unsigned short*)(smem + OFF_HP);

    float c = 0.f;
    float xi = __ldcg(&g_pre[0][(size_t)jglob * BB + bglob]);
    float xc = __ldcg(&g_pre[1][(size_t)jglob * BB + bglob]);
    float xo = __ldcg(&g_pre[2][(size_t)jglob * BB + bglob]);

    for (int t = 0; t < TT; t++) {
        // ---- per-warp poll of my half's 16 producer flags --------------------
        {
            const unsigned tgt = 64u * (unsigned)(t + 1);
            if (lane < 16) {
                const unsigned int* fp = &g_flag[g * 32 + half * 16 + lane];
                while (ld_acq(fp) < tgt) { }
            }
            __syncwarp();
        }

        // ---- stage h splits: T1 (commit), then T2 (commit) --------------------
        {
            const char* src = (const char*)&g_hs[g][t & 1][0][0][0];
#pragma unroll
            for (int i = 0; i < 4; i++) {          // T1
                const int m = tid + i * 256;
                const int b = m >> 6, kc = m & 63;
                cp16(sbase + OFF_T1 + b * RSTRB + kc * 16, src + (size_t)m * 16);
            }
            cp_commit();
#pragma unroll
            for (int i = 4; i < 8; i++) {          // T2
                const int m = tid + i * 256;
                const int cc = m & 1023;
                const int b = cc >> 6, kc = cc & 63;
                cp16(sbase + OFF_T2 + b * RSTRB + kc * 16,
                     src + (size_t)(BPG * DD * 2) + (size_t)cc * 16);
            }
            cp_commit();
        }

        float acc[2][4] = {};

        cp_wait<1>();
        __syncthreads();
        // ---- phase A: h1*U1 + h1*U2 (T1 only; T2 still in flight) ------------
#pragma unroll
        for (int kt = 0; kt < 16; kt++) {
            uint32_t a1[4];
            ldsm_x4(a1, sbase + OFF_T1 + kt * 32 + aoff);
#pragma unroll
            for (int nt = 0; nt < 2; nt++) {
                mma_bf16(acc[nt], a1, bc1[nt][kt]);
                mma_bf16(acc[nt], a1, bc2[nt][kt]);
            }
        }
        cp_wait<0>();
        __syncthreads();
        // ---- phase B: h2*U1 ---------------------------------------------------
#pragma unroll
        for (int kt = 0; kt < 16; kt++) {
            uint32_t a2[4];
            ldsm_x4(a2, sbase + OFF_T2 + kt * 32 + aoff);
#pragma unroll
            for (int nt = 0; nt < 2; nt++)
                mma_bf16(acc[nt], a2, bc1[nt][kt]);
        }

        // ---- partials ---------------------------------------------------------
        {
            const int gq = lane >> 2, c2 = (lane & 3) * 2;
#pragma unroll
            for (int nt = 0; nt < 2; nt++) {
                const int n0 = nh * 16 + nt * 8 + c2;
                *(float2*)&P[(kw * 16 + gq) * PSTR + n0] =
                    make_float2(acc[nt][0], acc[nt][1]);
                *(float2*)&P[(kw * 16 + gq + 8) * PSTR + n0] =
                    make_float2(acc[nt][2], acc[nt][3]);
            }
        }
        __syncthreads();

        // ---- gates (quirks: f uses xi; i has no U-bias) -----------------------
        {
            float pre[4];
#pragma unroll
            for (int ga = 0; ga < 4; ga++) {
                const int n = ga * 16 + jj;
                pre[ga] = P[bb * PSTR + n] + P[(16 + bb) * PSTR + n];
            }
            const float pi = xi + pre[0];
            const float pf = xi + pre[1] + bfb;
            const float pc = xc + pre[2] + bcb;
            const float po = xo + pre[3] + bob;
            const float ig = sigf(pi);
            const float fg = sigf(pf);
            const float gg = tanhfast(pc);
            const float og = sigf(po);
            c = fg * c + ig * gg;
            const float h = og * tanhfast(c);

            const __nv_bfloat16 h1 = __float2bfloat16(h);
            const __nv_bfloat16 h2 = __float2bfloat16(h - __bfloat162float(h1));
            HP[0 * 256 + bb * 16 + jj] = *(const unsigned short*)&h1;
            HP[1 * 256 + bb * 16 + jj] = *(const unsigned short*)&h2;
            HO[bb * 17 + jj] = h;
            CO[bb * 17 + jj] = c;
        }
        __syncthreads();

        // ---- publish + per-thread release -------------------------------------
        if (tid < 64) {
            const int s = tid >> 5, rem = tid & 31, b = rem >> 1, part = rem & 1;
            const uint4 v = *(const uint4*)(smem + OFF_HP + s * 512 + b * 32 + part * 16);
            *(uint4*)((char*)&g_hs[g][(t + 1) & 1][s][b][j0] + part * 16) = v;
            red_release(myflag);
        }

        // ---- overlap: outputs + next-x preload --------------------------------
        {
            const int m = tid & 127;
            const int ob = m >> 3, oj = (m & 7) * 2;
            const size_t obase = (size_t)(g * BPG + ob) * (TT * DD) +
                                 (size_t)t * DD + j0 + oj;
            const float* S = (tid < 128) ? HO : CO;
            float* O = (tid < 128) ? outH : outC;
            *(float2*)&O[obase] = make_float2(S[ob * 17 + oj], S[ob * 17 + oj + 1]);
        }
        if (t + 1 < TT) {
            const size_t p2 = (size_t)(t + 1) * (DD * BB) + (size_t)jglob * BB + bglob;
            xi = __ldcg(&g_pre[0][p2]);
            xc = __ldcg(&g_pre[1][p2]);
            xo = __ldcg(&g_pre[2][p2]);
        }
    }
}

// ---------------- launch -----------------------------------------------------
extern "C" void kernel_launch(void* const* d_in, const int* in_sizes, int n_in,
                              void* d_out, int out_size) {
    const float* X   = (const float*)d_in[0];
    const float* Wi  = (const float*)d_in[1];
    const float* bi  = (const float*)d_in[2];
    // d_in[3] = Wf, d_in[4] = bf: computed-but-unused in the reference
    const float* Wc  = (const float*)d_in[5];
    const float* bc  = (const float*)d_in[6];
    const float* Wo  = (const float*)d_in[7];
    const float* bo  = (const float*)d_in[8];
    const float* Ui  = (const float*)d_in[9];
    const float* Uf  = (const float*)d_in[10];
    const float* bUf = (const float*)d_in[11];
    const float* Uc  = (const float*)d_in[12];
    const float* bUc = (const float*)d_in[13];
    const float* Uo  = (const float*)d_in[14];
    const float* bUo = (const float*)d_in[15];

    float* outH = (float*)d_out;
    float* outC = outH + (size_t)BB * TT * DD;

    // dummy first: (a) inits scan state, (b) shifts the ncu capture slot so
    // launch #4 of the stream = the scan kernel (finally profiles it).
    dummy_init_kernel<<<(int)(sizeof(g_hs) / 16 + 255) / 256, 256>>>();

    split_kernel<<<(BB * TT * (DD / 4) + 255) / 256, 256>>>(X, Wi, Wc, Wo);

    cudaFuncSetAttribute(gemm_tc_kernel,
                         cudaFuncAttributeMaxDynamicSharedMemorySize, SMEM_GEMM);
    dim3 g1(DD / 64, (BB * TT) / 128, 3);
    gemm_tc_kernel<<<g1, 256, SMEM_GEMM>>>(bi, bc, bo);

    cudaFuncSetAttribute(lstm_scan_kernel,
                         cudaFuncAttributeMaxDynamicSharedMemorySize, SMEM_SCAN);
    lstm_scan_kernel<<<NG * CPG, 256, SMEM_SCAN>>>(Ui, Uf, Uc, Uo, bUf, bUc, bUo,
                                                   outH, outC);
}